// round 10
// baseline (speedup 1.0000x reference)
#include <cuda_runtime.h>
#include <cuda_fp16.h>
#include <stdint.h>
#include <math.h>

#define NN 50000
#define NE 800000
#define NF 512
#define NH 128
#define NL 16
#define TR 32            // fused-layer tile rows

typedef unsigned long long ull;

// ---------------- scratch (device globals: allocation-free) ----------------
__device__ int   g_deg[NN];
__device__ int   g_rowptr[NN + 1];
__device__ int   g_incl[NN];
__device__ int   g_bsum[64];
__device__ ull   g_ecw[NE];            // packed (col, weight)
__device__ float g_dinv[NN];
__device__ __align__(16) float g_h0[(size_t)NN * NH];          // fp32 anchor
__device__ __align__(16) __half g_h16A[(size_t)NN * NH];
__device__ __align__(16) __half g_h16B[(size_t)NN * NH];
__device__ __align__(16) __half g_w16[(size_t)NL * NH * NH];   // theta_l * W_l fp16
__device__ __align__(16) __half g_w0h[(size_t)NF * NH];        // fc0_w fp16
__device__ __align__(16) __half g_w1h[(size_t)NH * NH];        // fc1_w fp16

union H2U { unsigned u; __half2 h; };
__device__ __forceinline__ unsigned h2_to_u(__half2 h) { H2U x; x.h = h; return x.u; }
__device__ __forceinline__ __half2 u_to_h2(unsigned u) { H2U x; x.u = u; return x.h; }

// ---------------- tensor-core helpers ----------------
__device__ __forceinline__ void ldsm4(unsigned &r0, unsigned &r1, unsigned &r2, unsigned &r3, unsigned addr) {
    asm volatile("ldmatrix.sync.aligned.m8n8.x4.shared.b16 {%0,%1,%2,%3}, [%4];"
                 : "=r"(r0), "=r"(r1), "=r"(r2), "=r"(r3) : "r"(addr));
}
__device__ __forceinline__ void ldsm4t(unsigned &r0, unsigned &r1, unsigned &r2, unsigned &r3, unsigned addr) {
    asm volatile("ldmatrix.sync.aligned.m8n8.x4.trans.shared.b16 {%0,%1,%2,%3}, [%4];"
                 : "=r"(r0), "=r"(r1), "=r"(r2), "=r"(r3) : "r"(addr));
}
__device__ __forceinline__ void mma16816(float* c, unsigned a0, unsigned a1, unsigned a2, unsigned a3,
                                         unsigned b0, unsigned b1) {
    asm volatile("mma.sync.aligned.m16n8k16.row.col.f32.f16.f16.f32 "
                 "{%0,%1,%2,%3}, {%4,%5,%6,%7}, {%8,%9}, {%0,%1,%2,%3};"
                 : "+f"(c[0]), "+f"(c[1]), "+f"(c[2]), "+f"(c[3])
                 : "r"(a0), "r"(a1), "r"(a2), "r"(a3), "r"(b0), "r"(b1));
}

// ---------------- graph preprocessing ----------------
__global__ void k_zero() {
    int i = blockIdx.x * blockDim.x + threadIdx.x;
    if (i < NN) g_deg[i] = 0;
}
__global__ void k_count(const int* __restrict__ row) {
    int e = blockIdx.x * blockDim.x + threadIdx.x;
    if (e < NE) atomicAdd(&g_deg[row[e]], 1);
}

__global__ void __launch_bounds__(1024) k_scanA() {
    int t = threadIdx.x, b = blockIdx.x;
    int i = b * 1024 + t;
    int d = (i < NN) ? g_deg[i] : 0;
    if (i < NN) g_dinv[i] = rsqrtf((float)(d + 1));   // fused dinv (+1 self loop)
    int v = d;
#pragma unroll
    for (int o = 1; o < 32; o <<= 1) {
        int n = __shfl_up_sync(0xffffffffu, v, o);
        if ((t & 31) >= o) v += n;
    }
    __shared__ int ws[32];
    if ((t & 31) == 31) ws[t >> 5] = v;
    __syncthreads();
    if (t < 32) {
        int s = ws[t];
#pragma unroll
        for (int o = 1; o < 32; o <<= 1) {
            int n = __shfl_up_sync(0xffffffffu, s, o);
            if (t >= o) s += n;
        }
        ws[t] = s;
    }
    __syncthreads();
    if (t >= 32) v += ws[(t >> 5) - 1];
    if (i < NN) g_incl[i] = v;
    if (t == 1023) g_bsum[b] = v;
}

__global__ void k_scanB(int nblk) {
    __shared__ int s[64];
    int t = threadIdx.x;
    s[t] = (t < nblk) ? g_bsum[t] : 0;
    __syncthreads();
    for (int o = 1; o < 64; o <<= 1) {
        int n = (t >= o) ? s[t - o] : 0;
        __syncthreads();
        s[t] += n;
        __syncthreads();
    }
    if (t < nblk) g_bsum[t] = s[t];
}

__global__ void __launch_bounds__(1024) k_scanC() {
    int t = threadIdx.x, b = blockIdx.x;
    int i = b * 1024 + t;
    if (i < NN) {
        int off  = b ? g_bsum[b - 1] : 0;
        int incl = g_incl[i] + off;
        int excl = incl - g_deg[i];
        g_rowptr[i] = excl;
        g_deg[i]    = excl;
        if (i == NN - 1) g_rowptr[NN] = incl;
    }
}

__global__ void k_scatter(const int* __restrict__ row, const int* __restrict__ col) {
    int e = blockIdx.x * blockDim.x + threadIdx.x;
    if (e < NE) {
        int r = row[e], c = col[e];
        int p = atomicAdd(&g_deg[r], 1);
        float w = g_dinv[r] * g_dinv[c];
        g_ecw[p] = (ull)(unsigned)c | ((ull)__float_as_uint(w) << 32);
    }
}

__global__ void k_wcvt(const float* __restrict__ cw, const float* __restrict__ w0,
                       const float* __restrict__ w1) {
    int idx = blockIdx.x * blockDim.x + threadIdx.x;
    if (idx < NL * NH * NH) {
        int l = idx >> 14;
        float theta = logf(0.5f / (float)(l + 1) + 1.0f);
        g_w16[idx] = __float2half_rn(theta * cw[idx]);
    }
    if (idx < NF * NH) g_w0h[idx] = __float2half_rn(w0[idx]);
    if (idx < NH * NH) g_w1h[idx] = __float2half_rn(w1[idx]);
}

#define SPAD 72    // 64-wide A-tile row stride in halves (gemm0/final)
#define WPAD 136   // B-tile row stride in halves
#define KPAD 136   // fused A-tile (K=128) row stride in halves

// ---------------- GEMM0 (tensor core): h0 = relu(x @ W0 + b0) ----------------
__global__ void __launch_bounds__(256) k_gemm0_mma(const float* __restrict__ x,
                                                   const float* __restrict__ b0) {
    __shared__ __align__(16) __half Ash[64 * SPAD];
    __shared__ __align__(16) __half Wsh[64 * WPAD];
    int t = threadIdx.x, lane = t & 31, warp = t >> 5;
    int wr = warp & 3, wc = warp >> 2;
    int row0 = blockIdx.x * 64;

    float acc[8][4];
#pragma unroll
    for (int i = 0; i < 8; i++)
#pragma unroll
        for (int j = 0; j < 4; j++) acc[i][j] = 0.f;

    unsigned s_base = (unsigned)__cvta_generic_to_shared(Ash);
    unsigned w_base = (unsigned)__cvta_generic_to_shared(Wsh);

    for (int kc = 0; kc < NF; kc += 64) {
#pragma unroll
        for (int i = 0; i < 4; i++) {
            int idx = t + i * 256;
            int rr = idx >> 4, c4 = idx & 15;
            int r = row0 + rr;
            float4 v = make_float4(0.f, 0.f, 0.f, 0.f);
            if (r < NN) v = *(const float4*)(x + (size_t)r * NF + kc + (c4 << 2));
            uint2 p;
            p.x = h2_to_u(__floats2half2_rn(v.x, v.y));
            p.y = h2_to_u(__floats2half2_rn(v.z, v.w));
            *(uint2*)(Ash + rr * SPAD + (c4 << 2)) = p;
        }
#pragma unroll
        for (int i = 0; i < 4; i++) {
            int idx = t + i * 256;
            int rr = idx >> 4, c16 = idx & 15;
            uint4 v = *(const uint4*)(g_w0h + (size_t)(kc + rr) * NH + (c16 << 3));
            *(uint4*)(Wsh + rr * WPAD + (c16 << 3)) = v;
        }
        __syncthreads();
#pragma unroll
        for (int ks = 0; ks < 4; ks++) {
            int arow = wr * 16 + (lane & 7) + ((lane >> 3) & 1) * 8;
            int acol = ks * 16 + (lane >> 4) * 8;
            unsigned a0, a1, a2, a3;
            ldsm4(a0, a1, a2, a3, s_base + (unsigned)(arow * SPAD + acol) * 2u);
#pragma unroll
            for (int nt = 0; nt < 4; nt++) {
                int brow = ks * 16 + (lane & 15);
                int bcol = wc * 64 + nt * 16 + ((lane >> 4) & 1) * 8;
                unsigned b0r, b1r, b2r, b3r;
                ldsm4t(b0r, b1r, b2r, b3r, w_base + (unsigned)(brow * WPAD + bcol) * 2u);
                mma16816(acc[2 * nt],     a0, a1, a2, a3, b0r, b1r);
                mma16816(acc[2 * nt + 1], a0, a1, a2, a3, b2r, b3r);
            }
        }
        __syncthreads();
    }

    int rbase = row0 + wr * 16 + (lane >> 2);
#pragma unroll
    for (int nt = 0; nt < 8; nt++) {
        int n0 = wc * 64 + nt * 8 + (lane & 3) * 2;
        float2 bias = *(const float2*)(b0 + n0);
#pragma unroll
        for (int half = 0; half < 2; half++) {
            int r = rbase + half * 8;
            if (r < NN) {
                size_t off = (size_t)r * NH + n0;
                float2 o;
                o.x = fmaxf(acc[nt][2 * half]     + bias.x, 0.f);
                o.y = fmaxf(acc[nt][2 * half + 1] + bias.y, 0.f);
                *(float2*)(g_h0 + off) = o;
                *(unsigned*)(g_h16A + off) = h2_to_u(__floats2half2_rn(o.x, o.y));
            }
        }
    }
}

// ---------------- fused layer: 32-row tile, W resident, 4-chain gather ----------------
// smem: Ssh16 [32][136] fp16 (8.7KB) | Wsh [128][136] fp16 (34.8KB) = 43.5KB static
__global__ void __launch_bounds__(256, 4) k_fused(int l, float theta, int flag) {
    const __half2* __restrict__ hin16 = flag ? (const __half2*)g_h16B : (const __half2*)g_h16A;
    __half* __restrict__ hout16       = flag ? g_h16A : g_h16B;
    const __half* __restrict__ w16 = g_w16 + (size_t)l * NH * NH;

    __shared__ __align__(16) __half Ssh16[TR * KPAD];
    __shared__ __align__(16) __half Wsh[NH * WPAD];

    int t = threadIdx.x, lane = t & 31, warp = t >> 5;
    int row0 = blockIdx.x * TR;

    // ---- load full W (128x128) into smem ----
#pragma unroll
    for (int i = 0; i < 8; i++) {
        int idx = t + i * 256;           // 0..2047
        int rr = idx >> 4, c16 = idx & 15;
        uint4 v = *(const uint4*)(w16 + (size_t)rr * NH + (c16 << 3));
        *(uint4*)(Wsh + rr * WPAD + (c16 << 3)) = v;
    }

    // ---- gather: 4 rows per warp, branchless 4-chain ----
    {
        int e[4], en[4];
        float4 a[4];
#pragma unroll
        for (int c = 0; c < 4; c++) {
            int r = row0 + warp * 4 + c;
            a[c] = make_float4(0.f, 0.f, 0.f, 0.f);
            e[c] = 0; en[c] = 0;
            if (r < NN) {
                e[c] = g_rowptr[r]; en[c] = g_rowptr[r + 1];
                float di = g_dinv[r]; float w2 = di * di;
                uint2 sr = *(const uint2*)(hin16 + (size_t)r * 64 + (lane << 1));
                float2 s0 = __half22float2(u_to_h2(sr.x));
                float2 s1 = __half22float2(u_to_h2(sr.y));
                a[c] = make_float4(w2 * s0.x, w2 * s0.y, w2 * s1.x, w2 * s1.y);
            }
        }
        int nact;
        do {
            int   col[4];
            float w[4];
            nact = 0;
#pragma unroll
            for (int c = 0; c < 4; c++) {
                bool act = e[c] < en[c];
                int idx = act ? e[c] : 0;
                ull cw = g_ecw[idx];
                col[c] = (int)(unsigned)cw;
                w[c] = act ? __uint_as_float((unsigned)(cw >> 32)) : 0.f;
                e[c] += act;
                nact += act;
            }
#pragma unroll
            for (int c = 0; c < 4; c++) {
                uint2 raw = *(const uint2*)(hin16 + (size_t)col[c] * 64 + (lane << 1));
                float2 f0 = __half22float2(u_to_h2(raw.x));
                float2 f1 = __half22float2(u_to_h2(raw.y));
                a[c].x = fmaf(w[c], f0.x, a[c].x);
                a[c].y = fmaf(w[c], f0.y, a[c].y);
                a[c].z = fmaf(w[c], f1.x, a[c].z);
                a[c].w = fmaf(w[c], f1.y, a[c].w);
            }
        } while (nact);

        // S = 0.9*acc + 0.1*h0 -> fp16 smem
#pragma unroll
        for (int c = 0; c < 4; c++) {
            int rr = warp * 4 + c;
            int r = row0 + rr;
            uint2 p = make_uint2(0u, 0u);
            if (r < NN) {
                float4 h0v = *(const float4*)(g_h0 + (size_t)r * NH + (lane << 2));
                float4 S;
                S.x = 0.9f * a[c].x + 0.1f * h0v.x;
                S.y = 0.9f * a[c].y + 0.1f * h0v.y;
                S.z = 0.9f * a[c].z + 0.1f * h0v.z;
                S.w = 0.9f * a[c].w + 0.1f * h0v.w;
                p.x = h2_to_u(__floats2half2_rn(S.x, S.y));
                p.y = h2_to_u(__floats2half2_rn(S.z, S.w));
            }
            *(uint2*)(Ssh16 + rr * KPAD + (lane << 2)) = p;
        }
    }
    __syncthreads();

    // ---- MMA: 32x128 tile; warp = 16 rows x 32 cols ----
    int wr = warp & 1, wc = warp >> 1;
    float acc[4][4];
#pragma unroll
    for (int i = 0; i < 4; i++)
#pragma unroll
        for (int j = 0; j < 4; j++) acc[i][j] = 0.f;

    unsigned s_base = (unsigned)__cvta_generic_to_shared(Ssh16);
    unsigned w_base = (unsigned)__cvta_generic_to_shared(Wsh);

#pragma unroll
    for (int ks = 0; ks < 8; ks++) {
        int arow = wr * 16 + (lane & 7) + ((lane >> 3) & 1) * 8;
        int acol = ks * 16 + (lane >> 4) * 8;
        unsigned a0, a1, a2, a3;
        ldsm4(a0, a1, a2, a3, s_base + (unsigned)(arow * KPAD + acol) * 2u);
#pragma unroll
        for (int nt = 0; nt < 2; nt++) {
            int brow = ks * 16 + (lane & 15);
            int bcol = wc * 32 + nt * 16 + ((lane >> 4) & 1) * 8;
            unsigned b0, b1, b2, b3;
            ldsm4t(b0, b1, b2, b3, w_base + (unsigned)(brow * WPAD + bcol) * 2u);
            mma16816(acc[2 * nt],     a0, a1, a2, a3, b0, b1);
            mma16816(acc[2 * nt + 1], a0, a1, a2, a3, b2, b3);
        }
    }

    // ---- epilogue: h = relu(acc + (1-theta)*S16) ----
    float omt = 1.0f - theta;
    int rloc = wr * 16 + (lane >> 2);
#pragma unroll
    for (int nt = 0; nt < 4; nt++) {
        int n0 = wc * 32 + nt * 8 + (lane & 3) * 2;
#pragma unroll
        for (int half = 0; half < 2; half++) {
            int rl = rloc + half * 8;
            int r = row0 + rl;
            if (r < NN) {
                float2 s = __half22float2(u_to_h2(*(const unsigned*)(Ssh16 + rl * KPAD + n0)));
                float2 o;
                o.x = fmaxf(acc[nt][2 * half]     + omt * s.x, 0.f);
                o.y = fmaxf(acc[nt][2 * half + 1] + omt * s.y, 0.f);
                *(unsigned*)(hout16 + (size_t)r * NH + n0) = h2_to_u(__floats2half2_rn(o.x, o.y));
            }
        }
    }
}

// ---------------- final (tensor core): out = h16A @ fc1_w + b1 ----------------
__global__ void __launch_bounds__(256) k_final_mma(const float* __restrict__ b1,
                                                   float* __restrict__ out) {
    __shared__ __align__(16) __half Ash[64 * SPAD];
    __shared__ __align__(16) __half Wsh[64 * WPAD];
    int t = threadIdx.x, lane = t & 31, warp = t >> 5;
    int wr = warp & 3, wc = warp >> 2;
    int row0 = blockIdx.x * 64;

    float acc[8][4];
#pragma unroll
    for (int i = 0; i < 8; i++)
#pragma unroll
        for (int j = 0; j < 4; j++) acc[i][j] = 0.f;

    unsigned s_base = (unsigned)__cvta_generic_to_shared(Ash);
    unsigned w_base = (unsigned)__cvta_generic_to_shared(Wsh);

    for (int kc = 0; kc < NH; kc += 64) {
#pragma unroll
        for (int i = 0; i < 2; i++) {
            int idx = t + i * 256;
            int rr = idx >> 3, c8 = idx & 7;
            int r = row0 + rr;
            uint4 v = make_uint4(0u, 0u, 0u, 0u);
            if (r < NN) v = *(const uint4*)(g_h16A + (size_t)r * NH + kc + (c8 << 3));
            *(uint4*)(Ash + rr * SPAD + (c8 << 3)) = v;
        }
#pragma unroll
        for (int i = 0; i < 4; i++) {
            int idx = t + i * 256;
            int rr = idx >> 4, c16 = idx & 15;
            uint4 v = *(const uint4*)(g_w1h + (size_t)(kc + rr) * NH + (c16 << 3));
            *(uint4*)(Wsh + rr * WPAD + (c16 << 3)) = v;
        }
        __syncthreads();
#pragma unroll
        for (int ks = 0; ks < 4; ks++) {
            int arow = wr * 16 + (lane & 7) + ((lane >> 3) & 1) * 8;
            int acol = ks * 16 + (lane >> 4) * 8;
            unsigned a0, a1, a2, a3;
            ldsm4(a0, a1, a2, a3, s_base + (unsigned)(arow * SPAD + acol) * 2u);
#pragma unroll
            for (int nt = 0; nt < 4; nt++) {
                int brow = ks * 16 + (lane & 15);
                int bcol = wc * 64 + nt * 16 + ((lane >> 4) & 1) * 8;
                unsigned b0r, b1r, b2r, b3r;
                ldsm4t(b0r, b1r, b2r, b3r, w_base + (unsigned)(brow * WPAD + bcol) * 2u);
                mma16816(acc[2 * nt],     a0, a1, a2, a3, b0r, b1r);
                mma16816(acc[2 * nt + 1], a0, a1, a2, a3, b2r, b3r);
            }
        }
        __syncthreads();
    }

    int rbase = row0 + wr * 16 + (lane >> 2);
#pragma unroll
    for (int nt = 0; nt < 8; nt++) {
        int n0 = wc * 64 + nt * 8 + (lane & 3) * 2;
        float2 bias = *(const float2*)(b1 + n0);
#pragma unroll
        for (int half = 0; half < 2; half++) {
            int r = rbase + half * 8;
            if (r < NN) {
                size_t off = (size_t)r * NH + n0;
                float2 o;
                o.x = acc[nt][2 * half]     + bias.x;
                o.y = acc[nt][2 * half + 1] + bias.y;
                *(float2*)(out + off) = o;
            }
        }
    }
}

// ---------------- launch ----------------
extern "C" void kernel_launch(void* const* d_in, const int* in_sizes, int n_in,
                              void* d_out, int out_size) {
    const float* x    = (const float*)d_in[0];
    const int*   ei   = (const int*)d_in[1];
    const float* cw   = (const float*)d_in[2];
    const float* fc0w = (const float*)d_in[3];
    const float* fc0b = (const float*)d_in[4];
    const float* fc1w = (const float*)d_in[5];
    const float* fc1b = (const float*)d_in[6];
    float* out = (float*)d_out;

    const int* row = ei;
    const int* col = ei + NE;

    int nblk = (NN + 1023) / 1024;  // 49

    k_zero<<<(NN + 255) / 256, 256>>>();
    k_count<<<(NE + 255) / 256, 256>>>(row);
    k_scanA<<<nblk, 1024>>>();
    k_scanB<<<1, 64>>>(nblk);
    k_scanC<<<nblk, 1024>>>();
    k_scatter<<<(NE + 255) / 256, 256>>>(row, col);
    k_wcvt<<<(NL * NH * NH + 255) / 256, 256>>>(cw, fc0w, fc1w);

    int gB = (NN + 63) / 64;
    int gF = (NN + TR - 1) / TR;   // 1563

    k_gemm0_mma<<<gB, 256>>>(x, fc0b);

    for (int l = 0; l < NL; l++) {
        int flag = l & 1;
        float theta = logf(0.5f / (float)(l + 1) + 1.0f);
        k_fused<<<gF, 256>>>(l, theta, flag);
    }

    k_final_mma<<<gB, 256>>>(fc1b, out);
}

// round 12
// speedup vs baseline: 1.0060x; 1.0060x over previous
#include <cuda_runtime.h>
#include <cuda_fp16.h>
#include <stdint.h>
#include <math.h>

#define NN 50000
#define NE 800000
#define NF 512
#define NH 128
#define NL 16

typedef unsigned long long ull;

// ---------------- scratch (device globals: allocation-free) ----------------
__device__ int   g_deg[NN];
__device__ int   g_rowptr[NN + 1];
__device__ int   g_incl[NN];
__device__ int   g_bsum[64];
__device__ ull   g_ecw[NE];            // packed (col, weight)
__device__ float g_dinv[NN];
__device__ __align__(16) float g_h0[(size_t)NN * NH];          // fp32 anchor
__device__ __align__(16) __half g_h16A[(size_t)NN * NH];
__device__ __align__(16) __half g_h16B[(size_t)NN * NH];
__device__ __align__(16) __half g_w16[(size_t)NL * NH * NH];   // theta_l * W_l fp16
__device__ __align__(16) __half g_w0h[(size_t)NF * NH];        // fc0_w fp16
__device__ __align__(16) __half g_w1h[(size_t)NH * NH];        // fc1_w fp16

union H2U { unsigned u; __half2 h; };
__device__ __forceinline__ unsigned h2_to_u(__half2 h) { H2U x; x.h = h; return x.u; }
__device__ __forceinline__ __half2 u_to_h2(unsigned u) { H2U x; x.u = u; return x.h; }

// ---------------- tensor-core + async helpers ----------------
__device__ __forceinline__ void ldsm4(unsigned &r0, unsigned &r1, unsigned &r2, unsigned &r3, unsigned addr) {
    asm volatile("ldmatrix.sync.aligned.m8n8.x4.shared.b16 {%0,%1,%2,%3}, [%4];"
                 : "=r"(r0), "=r"(r1), "=r"(r2), "=r"(r3) : "r"(addr));
}
__device__ __forceinline__ void ldsm4t(unsigned &r0, unsigned &r1, unsigned &r2, unsigned &r3, unsigned addr) {
    asm volatile("ldmatrix.sync.aligned.m8n8.x4.trans.shared.b16 {%0,%1,%2,%3}, [%4];"
                 : "=r"(r0), "=r"(r1), "=r"(r2), "=r"(r3) : "r"(addr));
}
__device__ __forceinline__ void mma16816(float* c, unsigned a0, unsigned a1, unsigned a2, unsigned a3,
                                         unsigned b0, unsigned b1) {
    asm volatile("mma.sync.aligned.m16n8k16.row.col.f32.f16.f16.f32 "
                 "{%0,%1,%2,%3}, {%4,%5,%6,%7}, {%8,%9}, {%0,%1,%2,%3};"
                 : "+f"(c[0]), "+f"(c[1]), "+f"(c[2]), "+f"(c[3])
                 : "r"(a0), "r"(a1), "r"(a2), "r"(a3), "r"(b0), "r"(b1));
}
__device__ __forceinline__ void cp16(unsigned dst, const void* src) {
    asm volatile("cp.async.cg.shared.global [%0], [%1], 16;" :: "r"(dst), "l"(src));
}

// ---------------- graph preprocessing ----------------
__global__ void k_zero() {
    int i = blockIdx.x * blockDim.x + threadIdx.x;
    if (i < NN) g_deg[i] = 0;
}
__global__ void k_count(const int* __restrict__ row) {
    int e = blockIdx.x * blockDim.x + threadIdx.x;
    if (e < NE) atomicAdd(&g_deg[row[e]], 1);
}

__global__ void __launch_bounds__(1024) k_scanA() {
    int t = threadIdx.x, b = blockIdx.x;
    int i = b * 1024 + t;
    int d = (i < NN) ? g_deg[i] : 0;
    if (i < NN) g_dinv[i] = rsqrtf((float)(d + 1));   // fused dinv (+1 self loop)
    int v = d;
#pragma unroll
    for (int o = 1; o < 32; o <<= 1) {
        int n = __shfl_up_sync(0xffffffffu, v, o);
        if ((t & 31) >= o) v += n;
    }
    __shared__ int ws[32];
    if ((t & 31) == 31) ws[t >> 5] = v;
    __syncthreads();
    if (t < 32) {
        int s = ws[t];
#pragma unroll
        for (int o = 1; o < 32; o <<= 1) {
            int n = __shfl_up_sync(0xffffffffu, s, o);
            if (t >= o) s += n;
        }
        ws[t] = s;
    }
    __syncthreads();
    if (t >= 32) v += ws[(t >> 5) - 1];
    if (i < NN) g_incl[i] = v;
    if (t == 1023) g_bsum[b] = v;
}

__global__ void k_scanB(int nblk) {
    __shared__ int s[64];
    int t = threadIdx.x;
    s[t] = (t < nblk) ? g_bsum[t] : 0;
    __syncthreads();
    for (int o = 1; o < 64; o <<= 1) {
        int n = (t >= o) ? s[t - o] : 0;
        __syncthreads();
        s[t] += n;
        __syncthreads();
    }
    if (t < nblk) g_bsum[t] = s[t];
}

__global__ void __launch_bounds__(1024) k_scanC() {
    int t = threadIdx.x, b = blockIdx.x;
    int i = b * 1024 + t;
    if (i < NN) {
        int off  = b ? g_bsum[b - 1] : 0;
        int incl = g_incl[i] + off;
        int excl = incl - g_deg[i];
        g_rowptr[i] = excl;
        g_deg[i]    = excl;
        if (i == NN - 1) g_rowptr[NN] = incl;
    }
}

__global__ void k_scatter(const int* __restrict__ row, const int* __restrict__ col) {
    int e = blockIdx.x * blockDim.x + threadIdx.x;
    if (e < NE) {
        int r = row[e], c = col[e];
        int p = atomicAdd(&g_deg[r], 1);
        float w = g_dinv[r] * g_dinv[c];
        g_ecw[p] = (ull)(unsigned)c | ((ull)__float_as_uint(w) << 32);
    }
}

__global__ void k_wcvt(const float* __restrict__ cw, const float* __restrict__ w0,
                       const float* __restrict__ w1) {
    int idx = blockIdx.x * blockDim.x + threadIdx.x;
    if (idx < NL * NH * NH) {
        int l = idx >> 14;
        float theta = logf(0.5f / (float)(l + 1) + 1.0f);
        g_w16[idx] = __float2half_rn(theta * cw[idx]);
    }
    if (idx < NF * NH) g_w0h[idx] = __float2half_rn(w0[idx]);
    if (idx < NH * NH) g_w1h[idx] = __float2half_rn(w1[idx]);
}

#define SPAD 72    // 64-wide A-tile row stride in halves (gemm0/final)
#define WPAD 136   // B-tile row stride in halves
#define KPAD 136   // fused A-tile (K=128) row stride in halves

// ---------------- GEMM0 (tensor core): h0 = relu(x @ W0 + b0) ----------------
__global__ void __launch_bounds__(256) k_gemm0_mma(const float* __restrict__ x,
                                                   const float* __restrict__ b0) {
    __shared__ __align__(16) __half Ash[64 * SPAD];
    __shared__ __align__(16) __half Wsh[64 * WPAD];
    int t = threadIdx.x, lane = t & 31, warp = t >> 5;
    int wr = warp & 3, wc = warp >> 2;
    int row0 = blockIdx.x * 64;

    float acc[8][4];
#pragma unroll
    for (int i = 0; i < 8; i++)
#pragma unroll
        for (int j = 0; j < 4; j++) acc[i][j] = 0.f;

    unsigned s_base = (unsigned)__cvta_generic_to_shared(Ash);
    unsigned w_base = (unsigned)__cvta_generic_to_shared(Wsh);

    for (int kc = 0; kc < NF; kc += 64) {
#pragma unroll
        for (int i = 0; i < 4; i++) {
            int idx = t + i * 256;
            int rr = idx >> 4, c4 = idx & 15;
            int r = row0 + rr;
            float4 v = make_float4(0.f, 0.f, 0.f, 0.f);
            if (r < NN) v = *(const float4*)(x + (size_t)r * NF + kc + (c4 << 2));
            uint2 p;
            p.x = h2_to_u(__floats2half2_rn(v.x, v.y));
            p.y = h2_to_u(__floats2half2_rn(v.z, v.w));
            *(uint2*)(Ash + rr * SPAD + (c4 << 2)) = p;
        }
#pragma unroll
        for (int i = 0; i < 4; i++) {
            int idx = t + i * 256;
            int rr = idx >> 4, c16 = idx & 15;
            uint4 v = *(const uint4*)(g_w0h + (size_t)(kc + rr) * NH + (c16 << 3));
            *(uint4*)(Wsh + rr * WPAD + (c16 << 3)) = v;
        }
        __syncthreads();
#pragma unroll
        for (int ks = 0; ks < 4; ks++) {
            int arow = wr * 16 + (lane & 7) + ((lane >> 3) & 1) * 8;
            int acol = ks * 16 + (lane >> 4) * 8;
            unsigned a0, a1, a2, a3;
            ldsm4(a0, a1, a2, a3, s_base + (unsigned)(arow * SPAD + acol) * 2u);
#pragma unroll
            for (int nt = 0; nt < 4; nt++) {
                int brow = ks * 16 + (lane & 15);
                int bcol = wc * 64 + nt * 16 + ((lane >> 4) & 1) * 8;
                unsigned b0r, b1r, b2r, b3r;
                ldsm4t(b0r, b1r, b2r, b3r, w_base + (unsigned)(brow * WPAD + bcol) * 2u);
                mma16816(acc[2 * nt],     a0, a1, a2, a3, b0r, b1r);
                mma16816(acc[2 * nt + 1], a0, a1, a2, a3, b2r, b3r);
            }
        }
        __syncthreads();
    }

    int rbase = row0 + wr * 16 + (lane >> 2);
#pragma unroll
    for (int nt = 0; nt < 8; nt++) {
        int n0 = wc * 64 + nt * 8 + (lane & 3) * 2;
        float2 bias = *(const float2*)(b0 + n0);
#pragma unroll
        for (int half = 0; half < 2; half++) {
            int r = rbase + half * 8;
            if (r < NN) {
                size_t off = (size_t)r * NH + n0;
                float2 o;
                o.x = fmaxf(acc[nt][2 * half]     + bias.x, 0.f);
                o.y = fmaxf(acc[nt][2 * half + 1] + bias.y, 0.f);
                *(float2*)(g_h0 + off) = o;
                *(unsigned*)(g_h16A + off) = h2_to_u(__floats2half2_rn(o.x, o.y));
            }
        }
    }
}

// ---------------- fused layer: 64-row tile, async W preload, unrolled dual-chain gather ----------------
// dynamic smem: Ssh16 [64][136] fp16 (17408 B) | Wsh [128][136] fp16 (34816 B) = 52224 B
#define FUSED_SMEM (64 * KPAD * 2 + NH * WPAD * 2)

__global__ void __launch_bounds__(256, 4) k_fused(int l, float theta, int flag) {
    const __half2* __restrict__ hin16 = flag ? (const __half2*)g_h16B : (const __half2*)g_h16A;
    __half* __restrict__ hout16       = flag ? g_h16A : g_h16B;
    const __half* __restrict__ w16 = g_w16 + (size_t)l * NH * NH;

    extern __shared__ char smem[];
    __half* Ssh16 = (__half*)smem;
    __half* Wsh   = (__half*)(smem + 64 * KPAD * 2);

    int t = threadIdx.x, lane = t & 31, warp = t >> 5;
    int row0 = blockIdx.x * 64;

    unsigned s_base = (unsigned)__cvta_generic_to_shared(Ssh16);
    unsigned w_base = (unsigned)__cvta_generic_to_shared(Wsh);

    // ---- async preload of full W (128x128), overlapped with gather ----
#pragma unroll
    for (int i = 0; i < 8; i++) {
        int idx = t + i * 256;           // 0..2047
        int rr = idx >> 4, c16 = idx & 15;
        cp16(w_base + (unsigned)(rr * WPAD + (c16 << 3)) * 2u,
             w16 + (size_t)rr * NH + (c16 << 3));
    }
    asm volatile("cp.async.commit_group;");

    // ---- gather: dual-row per warp, 2-edge unroll per row (4 chains) ----
#pragma unroll 1
    for (int jp = 0; jp < 4; jp++) {
        int rrA = warp * 8 + jp * 2;
        int rrB = rrA + 1;
        int rA = row0 + rrA, rB = row0 + rrB;

        float4 aA = make_float4(0.f, 0.f, 0.f, 0.f);
        float4 aB = make_float4(0.f, 0.f, 0.f, 0.f);
        int e0 = 0, end0 = 0, e1 = 0, end1 = 0;

        if (rA < NN) {
            e0 = g_rowptr[rA]; end0 = g_rowptr[rA + 1];
            float di = g_dinv[rA]; float w2 = di * di;
            uint2 sr = *(const uint2*)(hin16 + (size_t)rA * 64 + (lane << 1));
            float2 s0 = __half22float2(u_to_h2(sr.x));
            float2 s1 = __half22float2(u_to_h2(sr.y));
            aA = make_float4(w2 * s0.x, w2 * s0.y, w2 * s1.x, w2 * s1.y);
        }
        if (rB < NN) {
            e1 = g_rowptr[rB]; end1 = g_rowptr[rB + 1];
            float di = g_dinv[rB]; float w2 = di * di;
            uint2 sr = *(const uint2*)(hin16 + (size_t)rB * 64 + (lane << 1));
            float2 s0 = __half22float2(u_to_h2(sr.x));
            float2 s1 = __half22float2(u_to_h2(sr.y));
            aB = make_float4(w2 * s0.x, w2 * s0.y, w2 * s1.x, w2 * s1.y);
        }

        // main loop: 2 edges per row per iteration -> 4 independent feature loads
        while (e0 + 2 <= end0 && e1 + 2 <= end1) {
            ull cwA0 = g_ecw[e0], cwA1 = g_ecw[e0 + 1];
            ull cwB0 = g_ecw[e1], cwB1 = g_ecw[e1 + 1];
            int cA0 = (int)(unsigned)cwA0, cA1 = (int)(unsigned)cwA1;
            int cB0 = (int)(unsigned)cwB0, cB1 = (int)(unsigned)cwB1;
            float wA0 = __uint_as_float((unsigned)(cwA0 >> 32));
            float wA1 = __uint_as_float((unsigned)(cwA1 >> 32));
            float wB0 = __uint_as_float((unsigned)(cwB0 >> 32));
            float wB1 = __uint_as_float((unsigned)(cwB1 >> 32));
            uint2 rA0 = *(const uint2*)(hin16 + (size_t)cA0 * 64 + (lane << 1));
            uint2 rA1 = *(const uint2*)(hin16 + (size_t)cA1 * 64 + (lane << 1));
            uint2 rB0 = *(const uint2*)(hin16 + (size_t)cB0 * 64 + (lane << 1));
            uint2 rB1 = *(const uint2*)(hin16 + (size_t)cB1 * 64 + (lane << 1));
            float2 fA0x = __half22float2(u_to_h2(rA0.x)), fA0y = __half22float2(u_to_h2(rA0.y));
            float2 fA1x = __half22float2(u_to_h2(rA1.x)), fA1y = __half22float2(u_to_h2(rA1.y));
            float2 fB0x = __half22float2(u_to_h2(rB0.x)), fB0y = __half22float2(u_to_h2(rB0.y));
            float2 fB1x = __half22float2(u_to_h2(rB1.x)), fB1y = __half22float2(u_to_h2(rB1.y));
            aA.x = fmaf(wA0, fA0x.x, aA.x); aA.y = fmaf(wA0, fA0x.y, aA.y);
            aA.z = fmaf(wA0, fA0y.x, aA.z); aA.w = fmaf(wA0, fA0y.y, aA.w);
            aA.x = fmaf(wA1, fA1x.x, aA.x); aA.y = fmaf(wA1, fA1x.y, aA.y);
            aA.z = fmaf(wA1, fA1y.x, aA.z); aA.w = fmaf(wA1, fA1y.y, aA.w);
            aB.x = fmaf(wB0, fB0x.x, aB.x); aB.y = fmaf(wB0, fB0x.y, aB.y);
            aB.z = fmaf(wB0, fB0y.x, aB.z); aB.w = fmaf(wB0, fB0y.y, aB.w);
            aB.x = fmaf(wB1, fB1x.x, aB.x); aB.y = fmaf(wB1, fB1x.y, aB.y);
            aB.z = fmaf(wB1, fB1y.x, aB.z); aB.w = fmaf(wB1, fB1y.y, aB.w);
            e0 += 2; e1 += 2;
        }
        // remainders
        while (e0 < end0) {
            ull cw = g_ecw[e0++];
            int   c  = (int)(unsigned)cw;
            float we = __uint_as_float((unsigned)(cw >> 32));
            uint2 raw = *(const uint2*)(hin16 + (size_t)c * 64 + (lane << 1));
            float2 f0 = __half22float2(u_to_h2(raw.x));
            float2 f1 = __half22float2(u_to_h2(raw.y));
            aA.x = fmaf(we, f0.x, aA.x); aA.y = fmaf(we, f0.y, aA.y);
            aA.z = fmaf(we, f1.x, aA.z); aA.w = fmaf(we, f1.y, aA.w);
        }
        while (e1 < end1) {
            ull cw = g_ecw[e1++];
            int   c  = (int)(unsigned)cw;
            float we = __uint_as_float((unsigned)(cw >> 32));
            uint2 raw = *(const uint2*)(hin16 + (size_t)c * 64 + (lane << 1));
            float2 f0 = __half22float2(u_to_h2(raw.x));
            float2 f1 = __half22float2(u_to_h2(raw.y));
            aB.x = fmaf(we, f0.x, aB.x); aB.y = fmaf(we, f0.y, aB.y);
            aB.z = fmaf(we, f1.x, aB.z); aB.w = fmaf(we, f1.y, aB.w);
        }

        // S = 0.9*acc + 0.1*h0 -> fp16 smem
        if (rA < NN) {
            float4 h0v = *(const float4*)(g_h0 + (size_t)rA * NH + (lane << 2));
            float4 S;
            S.x = 0.9f * aA.x + 0.1f * h0v.x;
            S.y = 0.9f * aA.y + 0.1f * h0v.y;
            S.z = 0.9f * aA.z + 0.1f * h0v.z;
            S.w = 0.9f * aA.w + 0.1f * h0v.w;
            uint2 p;
            p.x = h2_to_u(__floats2half2_rn(S.x, S.y));
            p.y = h2_to_u(__floats2half2_rn(S.z, S.w));
            *(uint2*)(Ssh16 + rrA * KPAD + (lane << 2)) = p;
        } else {
            *(uint2*)(Ssh16 + rrA * KPAD + (lane << 2)) = make_uint2(0u, 0u);
        }
        if (rB < NN) {
            float4 h0v = *(const float4*)(g_h0 + (size_t)rB * NH + (lane << 2));
            float4 S;
            S.x = 0.9f * aB.x + 0.1f * h0v.x;
            S.y = 0.9f * aB.y + 0.1f * h0v.y;
            S.z = 0.9f * aB.z + 0.1f * h0v.z;
            S.w = 0.9f * aB.w + 0.1f * h0v.w;
            uint2 p;
            p.x = h2_to_u(__floats2half2_rn(S.x, S.y));
            p.y = h2_to_u(__floats2half2_rn(S.z, S.w));
            *(uint2*)(Ssh16 + rrB * KPAD + (lane << 2)) = p;
        } else {
            *(uint2*)(Ssh16 + rrB * KPAD + (lane << 2)) = make_uint2(0u, 0u);
        }
    }
    asm volatile("cp.async.wait_group 0;");
    __syncthreads();

    // ---- MMA: 64x128 tile, straight K=128, no mid syncs ----
    int wr = warp & 3, wc = warp >> 2;
    float acc[8][4];
#pragma unroll
    for (int i = 0; i < 8; i++)
#pragma unroll
        for (int j = 0; j < 4; j++) acc[i][j] = 0.f;

#pragma unroll
    for (int ks = 0; ks < 8; ks++) {
        int arow = wr * 16 + (lane & 7) + ((lane >> 3) & 1) * 8;
        int acol = ks * 16 + (lane >> 4) * 8;
        unsigned a0, a1, a2, a3;
        ldsm4(a0, a1, a2, a3, s_base + (unsigned)(arow * KPAD + acol) * 2u);
#pragma unroll
        for (int nt = 0; nt < 4; nt++) {
            int brow = ks * 16 + (lane & 15);
            int bcol = wc * 64 + nt * 16 + ((lane >> 4) & 1) * 8;
            unsigned b0, b1, b2, b3;
            ldsm4t(b0, b1, b2, b3, w_base + (unsigned)(brow * WPAD + bcol) * 2u);
            mma16816(acc[2 * nt],     a0, a1, a2, a3, b0, b1);
            mma16816(acc[2 * nt + 1], a0, a1, a2, a3, b2, b3);
        }
    }

    // ---- epilogue: h = relu(acc + (1-theta)*S16) ----
    float omt = 1.0f - theta;
    int rloc = wr * 16 + (lane >> 2);
#pragma unroll
    for (int nt = 0; nt < 8; nt++) {
        int n0 = wc * 64 + nt * 8 + (lane & 3) * 2;
#pragma unroll
        for (int half = 0; half < 2; half++) {
            int rl = rloc + half * 8;
            int r = row0 + rl;
            if (r < NN) {
                float2 s = __half22float2(u_to_h2(*(const unsigned*)(Ssh16 + rl * KPAD + n0)));
                float2 o;
                o.x = fmaxf(acc[nt][2 * half]     + omt * s.x, 0.f);
                o.y = fmaxf(acc[nt][2 * half + 1] + omt * s.y, 0.f);
                *(unsigned*)(hout16 + (size_t)r * NH + n0) = h2_to_u(__floats2half2_rn(o.x, o.y));
            }
        }
    }
}

// ---------------- final (tensor core): out = h16A @ fc1_w + b1 ----------------
__global__ void __launch_bounds__(256) k_final_mma(const float* __restrict__ b1,
                                                   float* __restrict__ out) {
    __shared__ __align__(16) __half Ash[64 * SPAD];
    __shared__ __align__(16) __half Wsh[64 * WPAD];
    int t = threadIdx.x, lane = t & 31, warp = t >> 5;
    int wr = warp & 3, wc = warp >> 2;
    int row0 = blockIdx.x * 64;

    float acc[8][4];
#pragma unroll
    for (int i = 0; i < 8; i++)
#pragma unroll
        for (int j = 0; j < 4; j++) acc[i][j] = 0.f;

    unsigned s_base = (unsigned)__cvta_generic_to_shared(Ash);
    unsigned w_base = (unsigned)__cvta_generic_to_shared(Wsh);

    for (int kc = 0; kc < NH; kc += 64) {
#pragma unroll
        for (int i = 0; i < 2; i++) {
            int idx = t + i * 256;
            int rr = idx >> 3, c8 = idx & 7;
            int r = row0 + rr;
            uint4 v = make_uint4(0u, 0u, 0u, 0u);
            if (r < NN) v = *(const uint4*)(g_h16A + (size_t)r * NH + kc + (c8 << 3));
            *(uint4*)(Ash + rr * SPAD + (c8 << 3)) = v;
        }
#pragma unroll
        for (int i = 0; i < 4; i++) {
            int idx = t + i * 256;
            int rr = idx >> 4, c16 = idx & 15;
            uint4 v = *(const uint4*)(g_w1h + (size_t)(kc + rr) * NH + (c16 << 3));
            *(uint4*)(Wsh + rr * WPAD + (c16 << 3)) = v;
        }
        __syncthreads();
#pragma unroll
        for (int ks = 0; ks < 4; ks++) {
            int arow = wr * 16 + (lane & 7) + ((lane >> 3) & 1) * 8;
            int acol = ks * 16 + (lane >> 4) * 8;
            unsigned a0, a1, a2, a3;
            ldsm4(a0, a1, a2, a3, s_base + (unsigned)(arow * SPAD + acol) * 2u);
#pragma unroll
            for (int nt = 0; nt < 4; nt++) {
                int brow = ks * 16 + (lane & 15);
                int bcol = wc * 64 + nt * 16 + ((lane >> 4) & 1) * 8;
                unsigned b0r, b1r, b2r, b3r;
                ldsm4t(b0r, b1r, b2r, b3r, w_base + (unsigned)(brow * WPAD + bcol) * 2u);
                mma16816(acc[2 * nt],     a0, a1, a2, a3, b0r, b1r);
                mma16816(acc[2 * nt + 1], a0, a1, a2, a3, b2r, b3r);
            }
        }
        __syncthreads();
    }

    int rbase = row0 + wr * 16 + (lane >> 2);
#pragma unroll
    for (int nt = 0; nt < 8; nt++) {
        int n0 = wc * 64 + nt * 8 + (lane & 3) * 2;
        float2 bias = *(const float2*)(b1 + n0);
#pragma unroll
        for (int half = 0; half < 2; half++) {
            int r = rbase + half * 8;
            if (r < NN) {
                size_t off = (size_t)r * NH + n0;
                float2 o;
                o.x = acc[nt][2 * half]     + bias.x;
                o.y = acc[nt][2 * half + 1] + bias.y;
                *(float2*)(out + off) = o;
            }
        }
    }
}

// ---------------- launch ----------------
extern "C" void kernel_launch(void* const* d_in, const int* in_sizes, int n_in,
                              void* d_out, int out_size) {
    const float* x    = (const float*)d_in[0];
    const int*   ei   = (const int*)d_in[1];
    const float* cw   = (const float*)d_in[2];
    const float* fc0w = (const float*)d_in[3];
    const float* fc0b = (const float*)d_in[4];
    const float* fc1w = (const float*)d_in[5];
    const float* fc1b = (const float*)d_in[6];
    float* out = (float*)d_out;

    const int* row = ei;
    const int* col = ei + NE;

    cudaFuncSetAttribute(k_fused, cudaFuncAttributeMaxDynamicSharedMemorySize, FUSED_SMEM);

    int nblk = (NN + 1023) / 1024;  // 49

    k_zero<<<(NN + 255) / 256, 256>>>();
    k_count<<<(NE + 255) / 256, 256>>>(row);
    k_scanA<<<nblk, 1024>>>();
    k_scanB<<<1, 64>>>(nblk);
    k_scanC<<<nblk, 1024>>>();
    k_scatter<<<(NE + 255) / 256, 256>>>(row, col);
    k_wcvt<<<(NL * NH * NH + 255) / 256, 256>>>(cw, fc0w, fc1w);

    int gB = (NN + 63) / 64;   // 782

    k_gemm0_mma<<<gB, 256>>>(x, fc0b);

    for (int l = 0; l < NL; l++) {
        int flag = l & 1;
        float theta = logf(0.5f / (float)(l + 1) + 1.0f);
        k_fused<<<gB, 256, FUSED_SMEM>>>(l, theta, flag);
    }

    k_final_mma<<<gB, 256>>>(fc1b, out);
}

// round 14
// speedup vs baseline: 1.0308x; 1.0247x over previous
#include <cuda_runtime.h>
#include <cuda_fp16.h>
#include <stdint.h>
#include <math.h>

#define NN 50000
#define NE 800000
#define NF 512
#define NH 128
#define NL 16

typedef unsigned long long ull;

// ---------------- scratch (device globals: allocation-free) ----------------
__device__ int   g_deg[NN];
__device__ int   g_rowptr[NN + 1];
__device__ int   g_incl[NN];
__device__ int   g_bsum[64];
__device__ ull   g_ecw[NE];            // packed (col, weight)
__device__ float g_dinv[NN];
__device__ __align__(16) __half g_h016[(size_t)NN * NH];       // fp16 anchor
__device__ __align__(16) __half g_h16A[(size_t)NN * NH];
__device__ __align__(16) __half g_h16B[(size_t)NN * NH];
__device__ __align__(16) __half g_w16[(size_t)NL * NH * NH];   // theta_l * W_l fp16
__device__ __align__(16) __half g_w0h[(size_t)NF * NH];        // fc0_w fp16
__device__ __align__(16) __half g_w1h[(size_t)NH * NH];        // fc1_w fp16

union H2U { unsigned u; __half2 h; };
__device__ __forceinline__ unsigned h2_to_u(__half2 h) { H2U x; x.h = h; return x.u; }
__device__ __forceinline__ __half2 u_to_h2(unsigned u) { H2U x; x.u = u; return x.h; }

// ---------------- tensor-core + async helpers ----------------
__device__ __forceinline__ void ldsm4(unsigned &r0, unsigned &r1, unsigned &r2, unsigned &r3, unsigned addr) {
    asm volatile("ldmatrix.sync.aligned.m8n8.x4.shared.b16 {%0,%1,%2,%3}, [%4];"
                 : "=r"(r0), "=r"(r1), "=r"(r2), "=r"(r3) : "r"(addr));
}
__device__ __forceinline__ void ldsm4t(unsigned &r0, unsigned &r1, unsigned &r2, unsigned &r3, unsigned addr) {
    asm volatile("ldmatrix.sync.aligned.m8n8.x4.trans.shared.b16 {%0,%1,%2,%3}, [%4];"
                 : "=r"(r0), "=r"(r1), "=r"(r2), "=r"(r3) : "r"(addr));
}
__device__ __forceinline__ void mma16816(float* c, unsigned a0, unsigned a1, unsigned a2, unsigned a3,
                                         unsigned b0, unsigned b1) {
    asm volatile("mma.sync.aligned.m16n8k16.row.col.f32.f16.f16.f32 "
                 "{%0,%1,%2,%3}, {%4,%5,%6,%7}, {%8,%9}, {%0,%1,%2,%3};"
                 : "+f"(c[0]), "+f"(c[1]), "+f"(c[2]), "+f"(c[3])
                 : "r"(a0), "r"(a1), "r"(a2), "r"(a3), "r"(b0), "r"(b1));
}
__device__ __forceinline__ void cp16(unsigned dst, const void* src) {
    asm volatile("cp.async.cg.shared.global [%0], [%1], 16;" :: "r"(dst), "l"(src));
}

// ---------------- graph preprocessing ----------------
__global__ void k_zero() {
    int i = blockIdx.x * blockDim.x + threadIdx.x;
    if (i < NN) g_deg[i] = 0;
}
__global__ void k_count(const int* __restrict__ row) {
    int e = blockIdx.x * blockDim.x + threadIdx.x;
    if (e < NE) atomicAdd(&g_deg[row[e]], 1);
}

__global__ void __launch_bounds__(1024) k_scanA() {
    int t = threadIdx.x, b = blockIdx.x;
    int i = b * 1024 + t;
    int d = (i < NN) ? g_deg[i] : 0;
    if (i < NN) g_dinv[i] = rsqrtf((float)(d + 1));   // fused dinv (+1 self loop)
    int v = d;
#pragma unroll
    for (int o = 1; o < 32; o <<= 1) {
        int n = __shfl_up_sync(0xffffffffu, v, o);
        if ((t & 31) >= o) v += n;
    }
    __shared__ int ws[32];
    if ((t & 31) == 31) ws[t >> 5] = v;
    __syncthreads();
    if (t < 32) {
        int s = ws[t];
#pragma unroll
        for (int o = 1; o < 32; o <<= 1) {
            int n = __shfl_up_sync(0xffffffffu, s, o);
            if (t >= o) s += n;
        }
        ws[t] = s;
    }
    __syncthreads();
    if (t >= 32) v += ws[(t >> 5) - 1];
    if (i < NN) g_incl[i] = v;
    if (t == 1023) g_bsum[b] = v;
}

__global__ void k_scanB(int nblk) {
    __shared__ int s[64];
    int t = threadIdx.x;
    s[t] = (t < nblk) ? g_bsum[t] : 0;
    __syncthreads();
    for (int o = 1; o < 64; o <<= 1) {
        int n = (t >= o) ? s[t - o] : 0;
        __syncthreads();
        s[t] += n;
        __syncthreads();
    }
    if (t < nblk) g_bsum[t] = s[t];
}

__global__ void __launch_bounds__(1024) k_scanC() {
    int t = threadIdx.x, b = blockIdx.x;
    int i = b * 1024 + t;
    if (i < NN) {
        int off  = b ? g_bsum[b - 1] : 0;
        int incl = g_incl[i] + off;
        int excl = incl - g_deg[i];
        g_rowptr[i] = excl;
        g_deg[i]    = excl;
        if (i == NN - 1) g_rowptr[NN] = incl;
    }
}

__global__ void k_scatter(const int* __restrict__ row, const int* __restrict__ col) {
    int e = blockIdx.x * blockDim.x + threadIdx.x;
    if (e < NE) {
        int r = row[e], c = col[e];
        int p = atomicAdd(&g_deg[r], 1);
        float w = g_dinv[r] * g_dinv[c];
        g_ecw[p] = (ull)(unsigned)c | ((ull)__float_as_uint(w) << 32);
    }
}

__global__ void k_wcvt(const float* __restrict__ cw, const float* __restrict__ w0,
                       const float* __restrict__ w1) {
    int idx = blockIdx.x * blockDim.x + threadIdx.x;
    if (idx < NL * NH * NH) {
        int l = idx >> 14;
        float theta = logf(0.5f / (float)(l + 1) + 1.0f);
        g_w16[idx] = __float2half_rn(theta * cw[idx]);
    }
    if (idx < NF * NH) g_w0h[idx] = __float2half_rn(w0[idx]);
    if (idx < NH * NH) g_w1h[idx] = __float2half_rn(w1[idx]);
}

#define SPAD 72    // 64-wide A-tile row stride in halves (gemm0/final)
#define WPAD 136   // B-tile row stride in halves
#define KPAD 136   // fused A-tile (K=128) row stride in halves

// ---------------- GEMM0 (tensor core): h0 = relu(x @ W0 + b0) ----------------
__global__ void __launch_bounds__(256) k_gemm0_mma(const float* __restrict__ x,
                                                   const float* __restrict__ b0) {
    __shared__ __align__(16) __half Ash[64 * SPAD];
    __shared__ __align__(16) __half Wsh[64 * WPAD];
    int t = threadIdx.x, lane = t & 31, warp = t >> 5;
    int wr = warp & 3, wc = warp >> 2;
    int row0 = blockIdx.x * 64;

    float acc[8][4];
#pragma unroll
    for (int i = 0; i < 8; i++)
#pragma unroll
        for (int j = 0; j < 4; j++) acc[i][j] = 0.f;

    unsigned s_base = (unsigned)__cvta_generic_to_shared(Ash);
    unsigned w_base = (unsigned)__cvta_generic_to_shared(Wsh);

    for (int kc = 0; kc < NF; kc += 64) {
#pragma unroll
        for (int i = 0; i < 4; i++) {
            int idx = t + i * 256;
            int rr = idx >> 4, c4 = idx & 15;
            int r = row0 + rr;
            float4 v = make_float4(0.f, 0.f, 0.f, 0.f);
            if (r < NN) v = *(const float4*)(x + (size_t)r * NF + kc + (c4 << 2));
            uint2 p;
            p.x = h2_to_u(__floats2half2_rn(v.x, v.y));
            p.y = h2_to_u(__floats2half2_rn(v.z, v.w));
            *(uint2*)(Ash + rr * SPAD + (c4 << 2)) = p;
        }
#pragma unroll
        for (int i = 0; i < 4; i++) {
            int idx = t + i * 256;
            int rr = idx >> 4, c16 = idx & 15;
            uint4 v = *(const uint4*)(g_w0h + (size_t)(kc + rr) * NH + (c16 << 3));
            *(uint4*)(Wsh + rr * WPAD + (c16 << 3)) = v;
        }
        __syncthreads();
#pragma unroll
        for (int ks = 0; ks < 4; ks++) {
            int arow = wr * 16 + (lane & 7) + ((lane >> 3) & 1) * 8;
            int acol = ks * 16 + (lane >> 4) * 8;
            unsigned a0, a1, a2, a3;
            ldsm4(a0, a1, a2, a3, s_base + (unsigned)(arow * SPAD + acol) * 2u);
#pragma unroll
            for (int nt = 0; nt < 4; nt++) {
                int brow = ks * 16 + (lane & 15);
                int bcol = wc * 64 + nt * 16 + ((lane >> 4) & 1) * 8;
                unsigned b0r, b1r, b2r, b3r;
                ldsm4t(b0r, b1r, b2r, b3r, w_base + (unsigned)(brow * WPAD + bcol) * 2u);
                mma16816(acc[2 * nt],     a0, a1, a2, a3, b0r, b1r);
                mma16816(acc[2 * nt + 1], a0, a1, a2, a3, b2r, b3r);
            }
        }
        __syncthreads();
    }

    int rbase = row0 + wr * 16 + (lane >> 2);
#pragma unroll
    for (int nt = 0; nt < 8; nt++) {
        int n0 = wc * 64 + nt * 8 + (lane & 3) * 2;
        float2 bias = *(const float2*)(b0 + n0);
#pragma unroll
        for (int half = 0; half < 2; half++) {
            int r = rbase + half * 8;
            if (r < NN) {
                size_t off = (size_t)r * NH + n0;
                float2 o;
                o.x = fmaxf(acc[nt][2 * half]     + bias.x, 0.f);
                o.y = fmaxf(acc[nt][2 * half + 1] + bias.y, 0.f);
                unsigned p = h2_to_u(__floats2half2_rn(o.x, o.y));
                *(unsigned*)(g_h016 + off) = p;
                *(unsigned*)(g_h16A + off) = p;
            }
        }
    }
}

// ---------------- fused layer: 64-row tile, R9 gather, full-W cp.async resident ----------------
// dynamic smem: Ssh16 [64][136] (17408 B) | Wsh [128][136] (34816 B) = 52224 B
#define FUSED_SMEM (64 * KPAD * 2 + NH * WPAD * 2)

__global__ void __launch_bounds__(256, 4) k_fused(int l, float theta, int flag) {
    const __half2* __restrict__ hin16 = flag ? (const __half2*)g_h16B : (const __half2*)g_h16A;
    __half* __restrict__ hout16       = flag ? g_h16A : g_h16B;
    const __half* __restrict__ w16 = g_w16 + (size_t)l * NH * NH;

    extern __shared__ char smem[];
    __half* Ssh16 = (__half*)smem;
    __half* Wsh   = (__half*)(smem + 64 * KPAD * 2);

    int t = threadIdx.x, lane = t & 31, warp = t >> 5;
    int row0 = blockIdx.x * 64;

    unsigned s_base = (unsigned)__cvta_generic_to_shared(Ssh16);
    unsigned w_base = (unsigned)__cvta_generic_to_shared(Wsh);

    // ---- async preload of full W (128x128), overlapped with gather ----
#pragma unroll
    for (int i = 0; i < 8; i++) {
        int idx = t + i * 256;           // 0..2047
        int rr = idx >> 4, c16 = idx & 15;
        cp16(w_base + (unsigned)(rr * WPAD + (c16 << 3)) * 2u,
             w16 + (size_t)rr * NH + (c16 << 3));
    }
    asm volatile("cp.async.commit_group;");

    // ---- phase 1: gather S = 0.9*(Â h) + 0.1*h0 (R9 dual-chain loop) ----
#pragma unroll 1
    for (int jp = 0; jp < 4; jp++) {
        int rrA = warp * 8 + jp * 2;
        int rrB = rrA + 1;
        int rA = row0 + rrA, rB = row0 + rrB;

        float4 aA = make_float4(0.f, 0.f, 0.f, 0.f);
        float4 aB = make_float4(0.f, 0.f, 0.f, 0.f);
        int e0 = 0, end0 = 0, e1 = 0, end1 = 0;

        if (rA < NN) {
            e0 = g_rowptr[rA]; end0 = g_rowptr[rA + 1];
            float di = g_dinv[rA]; float w2 = di * di;
            uint2 sr = *(const uint2*)(hin16 + (size_t)rA * 64 + (lane << 1));
            float2 s0 = __half22float2(u_to_h2(sr.x));
            float2 s1 = __half22float2(u_to_h2(sr.y));
            aA = make_float4(w2 * s0.x, w2 * s0.y, w2 * s1.x, w2 * s1.y);
        }
        if (rB < NN) {
            e1 = g_rowptr[rB]; end1 = g_rowptr[rB + 1];
            float di = g_dinv[rB]; float w2 = di * di;
            uint2 sr = *(const uint2*)(hin16 + (size_t)rB * 64 + (lane << 1));
            float2 s0 = __half22float2(u_to_h2(sr.x));
            float2 s1 = __half22float2(u_to_h2(sr.y));
            aB = make_float4(w2 * s0.x, w2 * s0.y, w2 * s1.x, w2 * s1.y);
        }

        // interleaved dual-row edge loop (2 independent load chains)
#pragma unroll 2
        while (e0 < end0 && e1 < end1) {
            ull cwA = g_ecw[e0];
            ull cwB = g_ecw[e1];
            int   cA = (int)(unsigned)cwA;
            int   cB = (int)(unsigned)cwB;
            float wA = __uint_as_float((unsigned)(cwA >> 32));
            float wB = __uint_as_float((unsigned)(cwB >> 32));
            uint2 rawA = *(const uint2*)(hin16 + (size_t)cA * 64 + (lane << 1));
            uint2 rawB = *(const uint2*)(hin16 + (size_t)cB * 64 + (lane << 1));
            float2 fA0 = __half22float2(u_to_h2(rawA.x));
            float2 fA1 = __half22float2(u_to_h2(rawA.y));
            float2 fB0 = __half22float2(u_to_h2(rawB.x));
            float2 fB1 = __half22float2(u_to_h2(rawB.y));
            aA.x = fmaf(wA, fA0.x, aA.x); aA.y = fmaf(wA, fA0.y, aA.y);
            aA.z = fmaf(wA, fA1.x, aA.z); aA.w = fmaf(wA, fA1.y, aA.w);
            aB.x = fmaf(wB, fB0.x, aB.x); aB.y = fmaf(wB, fB0.y, aB.y);
            aB.z = fmaf(wB, fB1.x, aB.z); aB.w = fmaf(wB, fB1.y, aB.w);
            e0++; e1++;
        }
#pragma unroll 4
        while (e0 < end0) {
            ull cw = g_ecw[e0++];
            int   c  = (int)(unsigned)cw;
            float we = __uint_as_float((unsigned)(cw >> 32));
            uint2 raw = *(const uint2*)(hin16 + (size_t)c * 64 + (lane << 1));
            float2 f0 = __half22float2(u_to_h2(raw.x));
            float2 f1 = __half22float2(u_to_h2(raw.y));
            aA.x = fmaf(we, f0.x, aA.x); aA.y = fmaf(we, f0.y, aA.y);
            aA.z = fmaf(we, f1.x, aA.z); aA.w = fmaf(we, f1.y, aA.w);
        }
#pragma unroll 4
        while (e1 < end1) {
            ull cw = g_ecw[e1++];
            int   c  = (int)(unsigned)cw;
            float we = __uint_as_float((unsigned)(cw >> 32));
            uint2 raw = *(const uint2*)(hin16 + (size_t)c * 64 + (lane << 1));
            float2 f0 = __half22float2(u_to_h2(raw.x));
            float2 f1 = __half22float2(u_to_h2(raw.y));
            aB.x = fmaf(we, f0.x, aB.x); aB.y = fmaf(we, f0.y, aB.y);
            aB.z = fmaf(we, f1.x, aB.z); aB.w = fmaf(we, f1.y, aB.w);
        }

        // S = 0.9*acc + 0.1*h0(fp16) -> fp16 smem
        if (rA < NN) {
            uint2 h0r = *(const uint2*)(g_h016 + (size_t)rA * NH + (lane << 2));
            float2 h0a = __half22float2(u_to_h2(h0r.x));
            float2 h0b = __half22float2(u_to_h2(h0r.y));
            float4 S;
            S.x = 0.9f * aA.x + 0.1f * h0a.x;
            S.y = 0.9f * aA.y + 0.1f * h0a.y;
            S.z = 0.9f * aA.z + 0.1f * h0b.x;
            S.w = 0.9f * aA.w + 0.1f * h0b.y;
            uint2 p;
            p.x = h2_to_u(__floats2half2_rn(S.x, S.y));
            p.y = h2_to_u(__floats2half2_rn(S.z, S.w));
            *(uint2*)(Ssh16 + rrA * KPAD + (lane << 2)) = p;
        } else {
            *(uint2*)(Ssh16 + rrA * KPAD + (lane << 2)) = make_uint2(0u, 0u);
        }
        if (rB < NN) {
            uint2 h0r = *(const uint2*)(g_h016 + (size_t)rB * NH + (lane << 2));
            float2 h0a = __half22float2(u_to_h2(h0r.x));
            float2 h0b = __half22float2(u_to_h2(h0r.y));
            float4 S;
            S.x = 0.9f * aB.x + 0.1f * h0a.x;
            S.y = 0.9f * aB.y + 0.1f * h0a.y;
            S.z = 0.9f * aB.z + 0.1f * h0b.x;
            S.w = 0.9f * aB.w + 0.1f * h0b.y;
            uint2 p;
            p.x = h2_to_u(__floats2half2_rn(S.x, S.y));
            p.y = h2_to_u(__floats2half2_rn(S.z, S.w));
            *(uint2*)(Ssh16 + rrB * KPAD + (lane << 2)) = p;
        } else {
            *(uint2*)(Ssh16 + rrB * KPAD + (lane << 2)) = make_uint2(0u, 0u);
        }
    }
    asm volatile("cp.async.wait_group 0;");
    __syncthreads();

    // ---- phase 2: MMA, straight K=128, no mid syncs ----
    int wr = warp & 3, wc = warp >> 2;
    float acc[8][4];
#pragma unroll
    for (int i = 0; i < 8; i++)
#pragma unroll
        for (int j = 0; j < 4; j++) acc[i][j] = 0.f;

#pragma unroll
    for (int ks = 0; ks < 8; ks++) {
        int arow = wr * 16 + (lane & 7) + ((lane >> 3) & 1) * 8;
        int acol = ks * 16 + (lane >> 4) * 8;
        unsigned a0, a1, a2, a3;
        ldsm4(a0, a1, a2, a3, s_base + (unsigned)(arow * KPAD + acol) * 2u);
#pragma unroll
        for (int nt = 0; nt < 4; nt++) {
            int brow = ks * 16 + (lane & 15);
            int bcol = wc * 64 + nt * 16 + ((lane >> 4) & 1) * 8;
            unsigned b0, b1, b2, b3;
            ldsm4t(b0, b1, b2, b3, w_base + (unsigned)(brow * WPAD + bcol) * 2u);
            mma16816(acc[2 * nt],     a0, a1, a2, a3, b0, b1);
            mma16816(acc[2 * nt + 1], a0, a1, a2, a3, b2, b3);
        }
    }

    // ---- epilogue: h = relu(acc + (1-theta)*S16) ----
    float omt = 1.0f - theta;
    int rloc = wr * 16 + (lane >> 2);
#pragma unroll
    for (int nt = 0; nt < 8; nt++) {
        int n0 = wc * 64 + nt * 8 + (lane & 3) * 2;
#pragma unroll
        for (int half = 0; half < 2; half++) {
            int rl = rloc + half * 8;
            int r = row0 + rl;
            if (r < NN) {
                float2 s = __half22float2(u_to_h2(*(const unsigned*)(Ssh16 + rl * KPAD + n0)));
                float2 o;
                o.x = fmaxf(acc[nt][2 * half]     + omt * s.x, 0.f);
                o.y = fmaxf(acc[nt][2 * half + 1] + omt * s.y, 0.f);
                *(unsigned*)(hout16 + (size_t)r * NH + n0) = h2_to_u(__floats2half2_rn(o.x, o.y));
            }
        }
    }
}

// ---------------- final (tensor core): out = h16A @ fc1_w + b1 ----------------
__global__ void __launch_bounds__(256) k_final_mma(const float* __restrict__ b1,
                                                   float* __restrict__ out) {
    __shared__ __align__(16) __half Ash[64 * SPAD];
    __shared__ __align__(16) __half Wsh[64 * WPAD];
    int t = threadIdx.x, lane = t & 31, warp = t >> 5;
    int wr = warp & 3, wc = warp >> 2;
    int row0 = blockIdx.x * 64;

    float acc[8][4];
#pragma unroll
    for (int i = 0; i < 8; i++)
#pragma unroll
        for (int j = 0; j < 4; j++) acc[i][j] = 0.f;

    unsigned s_base = (unsigned)__cvta_generic_to_shared(Ash);
    unsigned w_base = (unsigned)__cvta_generic_to_shared(Wsh);

    for (int kc = 0; kc < NH; kc += 64) {
#pragma unroll
        for (int i = 0; i < 2; i++) {
            int idx = t + i * 256;
            int rr = idx >> 3, c8 = idx & 7;
            int r = row0 + rr;
            uint4 v = make_uint4(0u, 0u, 0u, 0u);
            if (r < NN) v = *(const uint4*)(g_h16A + (size_t)r * NH + kc + (c8 << 3));
            *(uint4*)(Ash + rr * SPAD + (c8 << 3)) = v;
        }
#pragma unroll
        for (int i = 0; i < 4; i++) {
            int idx = t + i * 256;
            int rr = idx >> 4, c16 = idx & 15;
            uint4 v = *(const uint4*)(g_w1h + (size_t)(kc + rr) * NH + (c16 << 3));
            *(uint4*)(Wsh + rr * WPAD + (c16 << 3)) = v;
        }
        __syncthreads();
#pragma unroll
        for (int ks = 0; ks < 4; ks++) {
            int arow = wr * 16 + (lane & 7) + ((lane >> 3) & 1) * 8;
            int acol = ks * 16 + (lane >> 4) * 8;
            unsigned a0, a1, a2, a3;
            ldsm4(a0, a1, a2, a3, s_base + (unsigned)(arow * SPAD + acol) * 2u);
#pragma unroll
            for (int nt = 0; nt < 4; nt++) {
                int brow = ks * 16 + (lane & 15);
                int bcol = wc * 64 + nt * 16 + ((lane >> 4) & 1) * 8;
                unsigned b0r, b1r, b2r, b3r;
                ldsm4t(b0r, b1r, b2r, b3r, w_base + (unsigned)(brow * WPAD + bcol) * 2u);
                mma16816(acc[2 * nt],     a0, a1, a2, a3, b0r, b1r);
                mma16816(acc[2 * nt + 1], a0, a1, a2, a3, b2r, b3r);
            }
        }
        __syncthreads();
    }

    int rbase = row0 + wr * 16 + (lane >> 2);
#pragma unroll
    for (int nt = 0; nt < 8; nt++) {
        int n0 = wc * 64 + nt * 8 + (lane & 3) * 2;
        float2 bias = *(const float2*)(b1 + n0);
#pragma unroll
        for (int half = 0; half < 2; half++) {
            int r = rbase + half * 8;
            if (r < NN) {
                size_t off = (size_t)r * NH + n0;
                float2 o;
                o.x = acc[nt][2 * half]     + bias.x;
                o.y = acc[nt][2 * half + 1] + bias.y;
                *(float2*)(out + off) = o;
            }
        }
    }
}

// ---------------- launch ----------------
extern "C" void kernel_launch(void* const* d_in, const int* in_sizes, int n_in,
                              void* d_out, int out_size) {
    const float* x    = (const float*)d_in[0];
    const int*   ei   = (const int*)d_in[1];
    const float* cw   = (const float*)d_in[2];
    const float* fc0w = (const float*)d_in[3];
    const float* fc0b = (const float*)d_in[4];
    const float* fc1w = (const float*)d_in[5];
    const float* fc1b = (const float*)d_in[6];
    float* out = (float*)d_out;

    const int* row = ei;
    const int* col = ei + NE;

    cudaFuncSetAttribute(k_fused, cudaFuncAttributeMaxDynamicSharedMemorySize, FUSED_SMEM);

    int nblk = (NN + 1023) / 1024;  // 49

    k_zero<<<(NN + 255) / 256, 256>>>();
    k_count<<<(NE + 255) / 256, 256>>>(row);
    k_scanA<<<nblk, 1024>>>();
    k_scanB<<<1, 64>>>(nblk);
    k_scanC<<<nblk, 1024>>>();
    k_scatter<<<(NE + 255) / 256, 256>>>(row, col);
    k_wcvt<<<(NL * NH * NH + 255) / 256, 256>>>(cw, fc0w, fc1w);

    int gB = (NN + 63) / 64;   // 782

    k_gemm0_mma<<<gB, 256>>>(x, fc0b);

    for (int l = 0; l < NL; l++) {
        int flag = l & 1;
        float theta = logf(0.5f / (float)(l + 1) + 1.0f);
        k_fused<<<gB, 256, FUSED_SMEM>>>(l, theta, flag);
    }

    k_final_mma<<<gB, 256>>>(fc1b, out);
}

// round 15
// speedup vs baseline: 1.0611x; 1.0293x over previous
#include <cuda_runtime.h>
#include <cuda_fp16.h>
#include <stdint.h>
#include <math.h>

#define NN 50000
#define NE 800000
#define NF 512
#define NH 128
#define NL 16

typedef unsigned long long ull;

// ---------------- scratch (device globals: allocation-free) ----------------
__device__ int   g_deg[NN];
__device__ int   g_rowptr[NN + 1];
__device__ int   g_incl[NN];
__device__ int   g_bsum[64];
__device__ ull   g_ecw[NE];            // packed (col, weight)
__device__ float g_dinv[NN];
__device__ __align__(16) __half g_h016[(size_t)NN * NH];       // fp16 anchor
__device__ __align__(16) __half g_h16A[(size_t)NN * NH];
__device__ __align__(16) __half g_h16B[(size_t)NN * NH];
__device__ __align__(16) __half g_w16[(size_t)NL * NH * NH];   // theta_l * W_l fp16
__device__ __align__(16) __half g_w0h[(size_t)NF * NH];        // fc0_w fp16
__device__ __align__(16) __half g_w1h[(size_t)NH * NH];        // fc1_w fp16

union H2U { unsigned u; __half2 h; };
__device__ __forceinline__ unsigned h2_to_u(__half2 h) { H2U x; x.h = h; return x.u; }
__device__ __forceinline__ __half2 u_to_h2(unsigned u) { H2U x; x.u = u; return x.h; }

// ---------------- tensor-core + async helpers ----------------
__device__ __forceinline__ void ldsm4(unsigned &r0, unsigned &r1, unsigned &r2, unsigned &r3, unsigned addr) {
    asm volatile("ldmatrix.sync.aligned.m8n8.x4.shared.b16 {%0,%1,%2,%3}, [%4];"
                 : "=r"(r0), "=r"(r1), "=r"(r2), "=r"(r3) : "r"(addr));
}
__device__ __forceinline__ void ldsm4t(unsigned &r0, unsigned &r1, unsigned &r2, unsigned &r3, unsigned addr) {
    asm volatile("ldmatrix.sync.aligned.m8n8.x4.trans.shared.b16 {%0,%1,%2,%3}, [%4];"
                 : "=r"(r0), "=r"(r1), "=r"(r2), "=r"(r3) : "r"(addr));
}
__device__ __forceinline__ void mma16816(float* c, unsigned a0, unsigned a1, unsigned a2, unsigned a3,
                                         unsigned b0, unsigned b1) {
    asm volatile("mma.sync.aligned.m16n8k16.row.col.f32.f16.f16.f32 "
                 "{%0,%1,%2,%3}, {%4,%5,%6,%7}, {%8,%9}, {%0,%1,%2,%3};"
                 : "+f"(c[0]), "+f"(c[1]), "+f"(c[2]), "+f"(c[3])
                 : "r"(a0), "r"(a1), "r"(a2), "r"(a3), "r"(b0), "r"(b1));
}
__device__ __forceinline__ void cp16(unsigned dst, const void* src) {
    asm volatile("cp.async.cg.shared.global [%0], [%1], 16;" :: "r"(dst), "l"(src));
}

// ---------------- graph preprocessing ----------------
__global__ void k_zero() {
    int i = blockIdx.x * blockDim.x + threadIdx.x;
    if (i < NN) g_deg[i] = 0;
}
__global__ void k_count(const int* __restrict__ row) {
    int e = blockIdx.x * blockDim.x + threadIdx.x;
    if (e < NE) atomicAdd(&g_deg[row[e]], 1);
}

__global__ void __launch_bounds__(1024) k_scanA() {
    int t = threadIdx.x, b = blockIdx.x;
    int i = b * 1024 + t;
    int d = (i < NN) ? g_deg[i] : 0;
    if (i < NN) g_dinv[i] = rsqrtf((float)(d + 1));   // fused dinv (+1 self loop)
    int v = d;
#pragma unroll
    for (int o = 1; o < 32; o <<= 1) {
        int n = __shfl_up_sync(0xffffffffu, v, o);
        if ((t & 31) >= o) v += n;
    }
    __shared__ int ws[32];
    if ((t & 31) == 31) ws[t >> 5] = v;
    __syncthreads();
    if (t < 32) {
        int s = ws[t];
#pragma unroll
        for (int o = 1; o < 32; o <<= 1) {
            int n = __shfl_up_sync(0xffffffffu, s, o);
            if (t >= o) s += n;
        }
        ws[t] = s;
    }
    __syncthreads();
    if (t >= 32) v += ws[(t >> 5) - 1];
    if (i < NN) g_incl[i] = v;
    if (t == 1023) g_bsum[b] = v;
}

__global__ void k_scanB(int nblk) {
    __shared__ int s[64];
    int t = threadIdx.x;
    s[t] = (t < nblk) ? g_bsum[t] : 0;
    __syncthreads();
    for (int o = 1; o < 64; o <<= 1) {
        int n = (t >= o) ? s[t - o] : 0;
        __syncthreads();
        s[t] += n;
        __syncthreads();
    }
    if (t < nblk) g_bsum[t] = s[t];
}

__global__ void __launch_bounds__(1024) k_scanC() {
    int t = threadIdx.x, b = blockIdx.x;
    int i = b * 1024 + t;
    if (i < NN) {
        int off  = b ? g_bsum[b - 1] : 0;
        int incl = g_incl[i] + off;
        int excl = incl - g_deg[i];
        g_rowptr[i] = excl;
        g_deg[i]    = excl;
        if (i == NN - 1) g_rowptr[NN] = incl;
    }
}

__global__ void k_scatter(const int* __restrict__ row, const int* __restrict__ col) {
    int e = blockIdx.x * blockDim.x + threadIdx.x;
    if (e < NE) {
        int r = row[e], c = col[e];
        int p = atomicAdd(&g_deg[r], 1);
        float w = g_dinv[r] * g_dinv[c];
        g_ecw[p] = (ull)(unsigned)c | ((ull)__float_as_uint(w) << 32);
    }
}

__global__ void k_wcvt(const float* __restrict__ cw, const float* __restrict__ w0,
                       const float* __restrict__ w1) {
    int idx = blockIdx.x * blockDim.x + threadIdx.x;
    if (idx < NL * NH * NH) {
        int l = idx >> 14;
        float theta = logf(0.5f / (float)(l + 1) + 1.0f);
        g_w16[idx] = __float2half_rn(theta * cw[idx]);
    }
    if (idx < NF * NH) g_w0h[idx] = __float2half_rn(w0[idx]);
    if (idx < NH * NH) g_w1h[idx] = __float2half_rn(w1[idx]);
}

#define SPAD 72    // 64-wide A-tile row stride in halves (gemm0/final)
#define WPAD 136   // B-tile row stride in halves
#define KPAD 136   // fused A-tile (K=128) row stride in halves

// ---------------- GEMM0 (tensor core): h0 = relu(x @ W0 + b0) ----------------
__global__ void __launch_bounds__(256) k_gemm0_mma(const float* __restrict__ x,
                                                   const float* __restrict__ b0) {
    __shared__ __align__(16) __half Ash[64 * SPAD];
    __shared__ __align__(16) __half Wsh[64 * WPAD];
    int t = threadIdx.x, lane = t & 31, warp = t >> 5;
    int wr = warp & 3, wc = warp >> 2;
    int row0 = blockIdx.x * 64;

    float acc[8][4];
#pragma unroll
    for (int i = 0; i < 8; i++)
#pragma unroll
        for (int j = 0; j < 4; j++) acc[i][j] = 0.f;

    unsigned s_base = (unsigned)__cvta_generic_to_shared(Ash);
    unsigned w_base = (unsigned)__cvta_generic_to_shared(Wsh);

    for (int kc = 0; kc < NF; kc += 64) {
#pragma unroll
        for (int i = 0; i < 4; i++) {
            int idx = t + i * 256;
            int rr = idx >> 4, c4 = idx & 15;
            int r = row0 + rr;
            float4 v = make_float4(0.f, 0.f, 0.f, 0.f);
            if (r < NN) v = *(const float4*)(x + (size_t)r * NF + kc + (c4 << 2));
            uint2 p;
            p.x = h2_to_u(__floats2half2_rn(v.x, v.y));
            p.y = h2_to_u(__floats2half2_rn(v.z, v.w));
            *(uint2*)(Ash + rr * SPAD + (c4 << 2)) = p;
        }
#pragma unroll
        for (int i = 0; i < 4; i++) {
            int idx = t + i * 256;
            int rr = idx >> 4, c16 = idx & 15;
            uint4 v = *(const uint4*)(g_w0h + (size_t)(kc + rr) * NH + (c16 << 3));
            *(uint4*)(Wsh + rr * WPAD + (c16 << 3)) = v;
        }
        __syncthreads();
#pragma unroll
        for (int ks = 0; ks < 4; ks++) {
            int arow = wr * 16 + (lane & 7) + ((lane >> 3) & 1) * 8;
            int acol = ks * 16 + (lane >> 4) * 8;
            unsigned a0, a1, a2, a3;
            ldsm4(a0, a1, a2, a3, s_base + (unsigned)(arow * SPAD + acol) * 2u);
#pragma unroll
            for (int nt = 0; nt < 4; nt++) {
                int brow = ks * 16 + (lane & 15);
                int bcol = wc * 64 + nt * 16 + ((lane >> 4) & 1) * 8;
                unsigned b0r, b1r, b2r, b3r;
                ldsm4t(b0r, b1r, b2r, b3r, w_base + (unsigned)(brow * WPAD + bcol) * 2u);
                mma16816(acc[2 * nt],     a0, a1, a2, a3, b0r, b1r);
                mma16816(acc[2 * nt + 1], a0, a1, a2, a3, b2r, b3r);
            }
        }
        __syncthreads();
    }

    int rbase = row0 + wr * 16 + (lane >> 2);
#pragma unroll
    for (int nt = 0; nt < 8; nt++) {
        int n0 = wc * 64 + nt * 8 + (lane & 3) * 2;
        float2 bias = *(const float2*)(b0 + n0);
#pragma unroll
        for (int half = 0; half < 2; half++) {
            int r = rbase + half * 8;
            if (r < NN) {
                size_t off = (size_t)r * NH + n0;
                float2 o;
                o.x = fmaxf(acc[nt][2 * half]     + bias.x, 0.f);
                o.y = fmaxf(acc[nt][2 * half + 1] + bias.y, 0.f);
                unsigned p = h2_to_u(__floats2half2_rn(o.x, o.y));
                *(unsigned*)(g_h016 + off) = p;
                *(unsigned*)(g_h16A + off) = p;
            }
        }
    }
}

// ---------------- fused layer: R9 shape (34.8 KB smem), chunk-0 W prefetch ----------------
__global__ void __launch_bounds__(256, 4) k_fused(int l, float theta, int flag) {
    const __half2* __restrict__ hin16 = flag ? (const __half2*)g_h16B : (const __half2*)g_h16A;
    __half* __restrict__ hout16       = flag ? g_h16A : g_h16B;
    const __half* __restrict__ w16 = g_w16 + (size_t)l * NH * NH;

    __shared__ __align__(16) __half Ssh16[64 * KPAD];
    __shared__ __align__(16) __half Wsh[64 * WPAD];

    int t = threadIdx.x, lane = t & 31, warp = t >> 5;
    int row0 = blockIdx.x * 64;

    unsigned s_base = (unsigned)__cvta_generic_to_shared(Ssh16);
    unsigned w_base = (unsigned)__cvta_generic_to_shared(Wsh);

    // ---- async prefetch of W chunk 0 (k rows 0..63), overlapped with gather ----
#pragma unroll
    for (int i = 0; i < 4; i++) {
        int idx = t + i * 256;           // 0..1023
        int rr = idx >> 4, c16 = idx & 15;
        cp16(w_base + (unsigned)(rr * WPAD + (c16 << 3)) * 2u,
             w16 + (size_t)rr * NH + (c16 << 3));
    }
    asm volatile("cp.async.commit_group;");

    // ---- phase 1: gather S = 0.9*(Â h) + 0.1*h0 (R9 dual-chain loop) ----
#pragma unroll 1
    for (int jp = 0; jp < 4; jp++) {
        int rrA = warp * 8 + jp * 2;
        int rrB = rrA + 1;
        int rA = row0 + rrA, rB = row0 + rrB;

        float4 aA = make_float4(0.f, 0.f, 0.f, 0.f);
        float4 aB = make_float4(0.f, 0.f, 0.f, 0.f);
        int e0 = 0, end0 = 0, e1 = 0, end1 = 0;

        if (rA < NN) {
            e0 = g_rowptr[rA]; end0 = g_rowptr[rA + 1];
            float di = g_dinv[rA]; float w2 = di * di;
            uint2 sr = *(const uint2*)(hin16 + (size_t)rA * 64 + (lane << 1));
            float2 s0 = __half22float2(u_to_h2(sr.x));
            float2 s1 = __half22float2(u_to_h2(sr.y));
            aA = make_float4(w2 * s0.x, w2 * s0.y, w2 * s1.x, w2 * s1.y);
        }
        if (rB < NN) {
            e1 = g_rowptr[rB]; end1 = g_rowptr[rB + 1];
            float di = g_dinv[rB]; float w2 = di * di;
            uint2 sr = *(const uint2*)(hin16 + (size_t)rB * 64 + (lane << 1));
            float2 s0 = __half22float2(u_to_h2(sr.x));
            float2 s1 = __half22float2(u_to_h2(sr.y));
            aB = make_float4(w2 * s0.x, w2 * s0.y, w2 * s1.x, w2 * s1.y);
        }

        // interleaved dual-row edge loop (2 independent load chains)
#pragma unroll 2
        while (e0 < end0 && e1 < end1) {
            ull cwA = g_ecw[e0];
            ull cwB = g_ecw[e1];
            int   cA = (int)(unsigned)cwA;
            int   cB = (int)(unsigned)cwB;
            float wA = __uint_as_float((unsigned)(cwA >> 32));
            float wB = __uint_as_float((unsigned)(cwB >> 32));
            uint2 rawA = *(const uint2*)(hin16 + (size_t)cA * 64 + (lane << 1));
            uint2 rawB = *(const uint2*)(hin16 + (size_t)cB * 64 + (lane << 1));
            float2 fA0 = __half22float2(u_to_h2(rawA.x));
            float2 fA1 = __half22float2(u_to_h2(rawA.y));
            float2 fB0 = __half22float2(u_to_h2(rawB.x));
            float2 fB1 = __half22float2(u_to_h2(rawB.y));
            aA.x = fmaf(wA, fA0.x, aA.x); aA.y = fmaf(wA, fA0.y, aA.y);
            aA.z = fmaf(wA, fA1.x, aA.z); aA.w = fmaf(wA, fA1.y, aA.w);
            aB.x = fmaf(wB, fB0.x, aB.x); aB.y = fmaf(wB, fB0.y, aB.y);
            aB.z = fmaf(wB, fB1.x, aB.z); aB.w = fmaf(wB, fB1.y, aB.w);
            e0++; e1++;
        }
#pragma unroll 4
        while (e0 < end0) {
            ull cw = g_ecw[e0++];
            int   c  = (int)(unsigned)cw;
            float we = __uint_as_float((unsigned)(cw >> 32));
            uint2 raw = *(const uint2*)(hin16 + (size_t)c * 64 + (lane << 1));
            float2 f0 = __half22float2(u_to_h2(raw.x));
            float2 f1 = __half22float2(u_to_h2(raw.y));
            aA.x = fmaf(we, f0.x, aA.x); aA.y = fmaf(we, f0.y, aA.y);
            aA.z = fmaf(we, f1.x, aA.z); aA.w = fmaf(we, f1.y, aA.w);
        }
#pragma unroll 4
        while (e1 < end1) {
            ull cw = g_ecw[e1++];
            int   c  = (int)(unsigned)cw;
            float we = __uint_as_float((unsigned)(cw >> 32));
            uint2 raw = *(const uint2*)(hin16 + (size_t)c * 64 + (lane << 1));
            float2 f0 = __half22float2(u_to_h2(raw.x));
            float2 f1 = __half22float2(u_to_h2(raw.y));
            aB.x = fmaf(we, f0.x, aB.x); aB.y = fmaf(we, f0.y, aB.y);
            aB.z = fmaf(we, f1.x, aB.z); aB.w = fmaf(we, f1.y, aB.w);
        }

        // S = 0.9*acc + 0.1*h0(fp16) -> fp16 smem
        if (rA < NN) {
            uint2 h0r = *(const uint2*)(g_h016 + (size_t)rA * NH + (lane << 2));
            float2 h0a = __half22float2(u_to_h2(h0r.x));
            float2 h0b = __half22float2(u_to_h2(h0r.y));
            float4 S;
            S.x = 0.9f * aA.x + 0.1f * h0a.x;
            S.y = 0.9f * aA.y + 0.1f * h0a.y;
            S.z = 0.9f * aA.z + 0.1f * h0b.x;
            S.w = 0.9f * aA.w + 0.1f * h0b.y;
            uint2 p;
            p.x = h2_to_u(__floats2half2_rn(S.x, S.y));
            p.y = h2_to_u(__floats2half2_rn(S.z, S.w));
            *(uint2*)(Ssh16 + rrA * KPAD + (lane << 2)) = p;
        } else {
            *(uint2*)(Ssh16 + rrA * KPAD + (lane << 2)) = make_uint2(0u, 0u);
        }
        if (rB < NN) {
            uint2 h0r = *(const uint2*)(g_h016 + (size_t)rB * NH + (lane << 2));
            float2 h0a = __half22float2(u_to_h2(h0r.x));
            float2 h0b = __half22float2(u_to_h2(h0r.y));
            float4 S;
            S.x = 0.9f * aB.x + 0.1f * h0a.x;
            S.y = 0.9f * aB.y + 0.1f * h0a.y;
            S.z = 0.9f * aB.z + 0.1f * h0b.x;
            S.w = 0.9f * aB.w + 0.1f * h0b.y;
            uint2 p;
            p.x = h2_to_u(__floats2half2_rn(S.x, S.y));
            p.y = h2_to_u(__floats2half2_rn(S.z, S.w));
            *(uint2*)(Ssh16 + rrB * KPAD + (lane << 2)) = p;
        } else {
            *(uint2*)(Ssh16 + rrB * KPAD + (lane << 2)) = make_uint2(0u, 0u);
        }
    }
    asm volatile("cp.async.wait_group 0;");
    __syncthreads();

    // ---- phase 2: HMMA over 2 K-chunks (W chunk 0 prefetched) ----
    int wr = warp & 3, wc = warp >> 2;
    float acc[8][4];
#pragma unroll
    for (int i = 0; i < 8; i++)
#pragma unroll
        for (int j = 0; j < 4; j++) acc[i][j] = 0.f;

    for (int kc = 0; kc < NH; kc += 64) {
        if (kc > 0) {
            __syncthreads();
#pragma unroll
            for (int i = 0; i < 4; i++) {
                int idx = t + i * 256;
                int rr = idx >> 4, c16 = idx & 15;
                uint4 v = *(const uint4*)(w16 + (size_t)(kc + rr) * NH + (c16 << 3));
                *(uint4*)(Wsh + rr * WPAD + (c16 << 3)) = v;
            }
            __syncthreads();
        }
#pragma unroll
        for (int ks = 0; ks < 4; ks++) {
            int arow = wr * 16 + (lane & 7) + ((lane >> 3) & 1) * 8;
            int acol = kc + ks * 16 + (lane >> 4) * 8;
            unsigned a0, a1, a2, a3;
            ldsm4(a0, a1, a2, a3, s_base + (unsigned)(arow * KPAD + acol) * 2u);
#pragma unroll
            for (int nt = 0; nt < 4; nt++) {
                int brow = ks * 16 + (lane & 15);
                int bcol = wc * 64 + nt * 16 + ((lane >> 4) & 1) * 8;
                unsigned b0, b1, b2, b3;
                ldsm4t(b0, b1, b2, b3, w_base + (unsigned)(brow * WPAD + bcol) * 2u);
                mma16816(acc[2 * nt],     a0, a1, a2, a3, b0, b1);
                mma16816(acc[2 * nt + 1], a0, a1, a2, a3, b2, b3);
            }
        }
    }

    // ---- epilogue: h = relu(acc + (1-theta)*S16) ----
    float omt = 1.0f - theta;
    int rloc = wr * 16 + (lane >> 2);
#pragma unroll
    for (int nt = 0; nt < 8; nt++) {
        int n0 = wc * 64 + nt * 8 + (lane & 3) * 2;
#pragma unroll
        for (int half = 0; half < 2; half++) {
            int rl = rloc + half * 8;
            int r = row0 + rl;
            if (r < NN) {
                float2 s = __half22float2(u_to_h2(*(const unsigned*)(Ssh16 + rl * KPAD + n0)));
                float2 o;
                o.x = fmaxf(acc[nt][2 * half]     + omt * s.x, 0.f);
                o.y = fmaxf(acc[nt][2 * half + 1] + omt * s.y, 0.f);
                *(unsigned*)(hout16 + (size_t)r * NH + n0) = h2_to_u(__floats2half2_rn(o.x, o.y));
            }
        }
    }
}

// ---------------- final (tensor core): out = h16A @ fc1_w + b1 ----------------
__global__ void __launch_bounds__(256) k_final_mma(const float* __restrict__ b1,
                                                   float* __restrict__ out) {
    __shared__ __align__(16) __half Ash[64 * SPAD];
    __shared__ __align__(16) __half Wsh[64 * WPAD];
    int t = threadIdx.x, lane = t & 31, warp = t >> 5;
    int wr = warp & 3, wc = warp >> 2;
    int row0 = blockIdx.x * 64;

    float acc[8][4];
#pragma unroll
    for (int i = 0; i < 8; i++)
#pragma unroll
        for (int j = 0; j < 4; j++) acc[i][j] = 0.f;

    unsigned s_base = (unsigned)__cvta_generic_to_shared(Ash);
    unsigned w_base = (unsigned)__cvta_generic_to_shared(Wsh);

    for (int kc = 0; kc < NH; kc += 64) {
#pragma unroll
        for (int i = 0; i < 2; i++) {
            int idx = t + i * 256;
            int rr = idx >> 3, c8 = idx & 7;
            int r = row0 + rr;
            uint4 v = make_uint4(0u, 0u, 0u, 0u);
            if (r < NN) v = *(const uint4*)(g_h16A + (size_t)r * NH + kc + (c8 << 3));
            *(uint4*)(Ash + rr * SPAD + (c8 << 3)) = v;
        }
#pragma unroll
        for (int i = 0; i < 4; i++) {
            int idx = t + i * 256;
            int rr = idx >> 4, c16 = idx & 15;
            uint4 v = *(const uint4*)(g_w1h + (size_t)(kc + rr) * NH + (c16 << 3));
            *(uint4*)(Wsh + rr * WPAD + (c16 << 3)) = v;
        }
        __syncthreads();
#pragma unroll
        for (int ks = 0; ks < 4; ks++) {
            int arow = wr * 16 + (lane & 7) + ((lane >> 3) & 1) * 8;
            int acol = ks * 16 + (lane >> 4) * 8;
            unsigned a0, a1, a2, a3;
            ldsm4(a0, a1, a2, a3, s_base + (unsigned)(arow * SPAD + acol) * 2u);
#pragma unroll
            for (int nt = 0; nt < 4; nt++) {
                int brow = ks * 16 + (lane & 15);
                int bcol = wc * 64 + nt * 16 + ((lane >> 4) & 1) * 8;
                unsigned b0r, b1r, b2r, b3r;
                ldsm4t(b0r, b1r, b2r, b3r, w_base + (unsigned)(brow * WPAD + bcol) * 2u);
                mma16816(acc[2 * nt],     a0, a1, a2, a3, b0r, b1r);
                mma16816(acc[2 * nt + 1], a0, a1, a2, a3, b2r, b3r);
            }
        }
        __syncthreads();
    }

    int rbase = row0 + wr * 16 + (lane >> 2);
#pragma unroll
    for (int nt = 0; nt < 8; nt++) {
        int n0 = wc * 64 + nt * 8 + (lane & 3) * 2;
        float2 bias = *(const float2*)(b1 + n0);
#pragma unroll
        for (int half = 0; half < 2; half++) {
            int r = rbase + half * 8;
            if (r < NN) {
                size_t off = (size_t)r * NH + n0;
                float2 o;
                o.x = acc[nt][2 * half]     + bias.x;
                o.y = acc[nt][2 * half + 1] + bias.y;
                *(float2*)(out + off) = o;
            }
        }
    }
}

// ---------------- launch ----------------
extern "C" void kernel_launch(void* const* d_in, const int* in_sizes, int n_in,
                              void* d_out, int out_size) {
    const float* x    = (const float*)d_in[0];
    const int*   ei   = (const int*)d_in[1];
    const float* cw   = (const float*)d_in[2];
    const float* fc0w = (const float*)d_in[3];
    const float* fc0b = (const float*)d_in[4];
    const float* fc1w = (const float*)d_in[5];
    const float* fc1b = (const float*)d_in[6];
    float* out = (float*)d_out;

    const int* row = ei;
    const int* col = ei + NE;

    int nblk = (NN + 1023) / 1024;  // 49

    k_zero<<<(NN + 255) / 256, 256>>>();
    k_count<<<(NE + 255) / 256, 256>>>(row);
    k_scanA<<<nblk, 1024>>>();
    k_scanB<<<1, 64>>>(nblk);
    k_scanC<<<nblk, 1024>>>();
    k_scatter<<<(NE + 255) / 256, 256>>>(row, col);
    k_wcvt<<<(NL * NH * NH + 255) / 256, 256>>>(cw, fc0w, fc1w);

    int gB = (NN + 63) / 64;   // 782

    k_gemm0_mma<<<gB, 256>>>(x, fc0b);

    for (int l = 0; l < NL; l++) {
        int flag = l & 1;
        float theta = logf(0.5f / (float)(l + 1) + 1.0f);
        k_fused<<<gB, 256>>>(l, theta, flag);
    }

    k_final_mma<<<gB, 256>>>(fc1b, out);
}